// round 8
// baseline (speedup 1.0000x reference)
#include <cuda_runtime.h>
#include <cuda_bf16.h>
#include <math.h>

// Problem constants (fixed by reference setup_inputs)
#define BB 8
#define TT 16
#define CC 64
#define NN 4096          // H*W
#define KSEL 2048        // keep_k = N*(1-0.5)

#define CHUNKB 2                         // batches per chunk
#define NCHUNK (BB / CHUNKB)             // 4 chunks
#define BLKS_PER_BATCH 64                // K1: 64 blocks x 1024 thr = 16*4096 partials

// Scratch (device globals — no allocation allowed)
__device__ float g_partial[BB * TT * NN];        // sqrt(sum_c x^2) per (b,t,n)
__device__ unsigned g_maskbits[BB * (NN / 32)];  // 1 bit per (b,n)
__device__ int g_cnt[BB];                        // per-batch block counters (self-resetting)

__device__ __forceinline__ unsigned long long warp_sum_u64(unsigned long long v) {
#pragma unroll
    for (int d = 16; d; d >>= 1) v += __shfl_xor_sync(0xffffffffu, v, d);
    return v;
}

// ---------------------------------------------------------------------------
// Verified select body (R4/R5 form): exact per-batch top-K -> mask bits.
// Runs with all 1024 threads of one block. Atomic-free 2-bit radix select.
// ---------------------------------------------------------------------------
__device__ void select_body(int b) {
    __shared__ unsigned long long s_red64[2][32];
    __shared__ unsigned s_u32[66];
    __shared__ unsigned s_mask[NN / 32];
    __shared__ int s_scan[32];
    __shared__ int s_int[1];

    const int j    = threadIdx.x;              // 0..1023
    const int lane = j & 31;
    const int wid  = j >> 5;

    // --- scores: 4 per thread, sequential over t (bit-exact vs reference) ---
    const float4* part = (const float4*)g_partial;
    float s0 = 0.f, s1 = 0.f, s2 = 0.f, s3 = 0.f;
#pragma unroll
    for (int t = 0; t < TT; ++t) {
        float4 f = part[(size_t)(b * TT + t) * (NN / 4) + j];
        s0 += f.x; s1 += f.y; s2 += f.z; s3 += f.w;
    }
    const float inv = 1.0f / (float)TT;
    unsigned u0 = __float_as_uint(s0 * inv);
    unsigned u1 = __float_as_uint(s1 * inv);
    unsigned u2 = __float_as_uint(s2 * inv);
    unsigned u3 = __float_as_uint(s3 * inv);

    if (j < NN / 32) s_mask[j] = 0u;

    // --- block OR / AND of all score bits ---
    unsigned ov = u0 | u1 | u2 | u3;
    unsigned av = u0 & u1 & u2 & u3;
#pragma unroll
    for (int d = 16; d; d >>= 1) {
        ov |= __shfl_xor_sync(0xffffffffu, ov, d);
        av &= __shfl_xor_sync(0xffffffffu, av, d);
    }
    if (lane == 0) { s_u32[wid] = ov; s_u32[32 + wid] = av; }
    __syncthreads();
    {
        unsigned o2 = s_u32[lane], a2 = s_u32[32 + lane];
#pragma unroll
        for (int d = 16; d; d >>= 1) {
            o2 |= __shfl_xor_sync(0xffffffffu, o2, d);
            a2 &= __shfl_xor_sync(0xffffffffu, a2, d);
        }
        if (j == 0) { s_u32[64] = o2; s_u32[65] = a2; }
    }
    __syncthreads();
    const unsigned orv  = s_u32[64];
    const unsigned andv = s_u32[65];
    const unsigned diff = orv ^ andv;

    // --- 2-bit radix select: largest thr with count(u >= thr) >= KSEL ---
    unsigned thr = 0u;
    int par = 0;
#pragma unroll
    for (int p = 15; p >= 0; --p) {
        unsigned m2 = 3u << (2 * p);
        if ((diff & m2) == 0u) {               // both bits uniform across block
            thr |= (andv & m2);
            continue;
        }
        unsigned c1 = thr | (1u << (2 * p));
        unsigned c2 = thr | (2u << (2 * p));
        unsigned c3 = thr | (3u << (2 * p));
        int n1 = (u0 >= c1) + (u1 >= c1) + (u2 >= c1) + (u3 >= c1);
        int n2 = (u0 >= c2) + (u1 >= c2) + (u2 >= c2) + (u3 >= c2);
        int n3 = (u0 >= c3) + (u1 >= c3) + (u2 >= c3) + (u3 >= c3);
        unsigned long long pk = (unsigned long long)n1
                              | ((unsigned long long)n2 << 20)
                              | ((unsigned long long)n3 << 40);
        pk = warp_sum_u64(pk);
        if (lane == 0) s_red64[par][wid] = pk;
        __syncthreads();
        unsigned long long tot = warp_sum_u64(s_red64[par][lane]);
        int N1 = (int)(tot & 0xFFFFFull);
        int N2 = (int)((tot >> 20) & 0xFFFFFull);
        int N3 = (int)((tot >> 40) & 0xFFFFFull);
        if      (N3 >= KSEL) thr = c3;
        else if (N2 >= KSEL) thr = c2;
        else if (N1 >= KSEL) thr = c1;
        par ^= 1;
    }
    __syncthreads();   // protect s_red64 before reuse below

    // --- strictly-greater count (ties admitted by lowest index) ---
    {
        unsigned long long pk =
            (unsigned long long)((u0 > thr) + (u1 > thr) + (u2 > thr) + (u3 > thr));
        pk = warp_sum_u64(pk);
        if (lane == 0) s_red64[0][wid] = pk;
        __syncthreads();
        unsigned long long tot = warp_sum_u64(s_red64[0][lane]);
        if (j == 0) s_int[0] = (int)tot;
        __syncthreads();
    }
    int need = KSEL - s_int[0];

    // --- exclusive scan over threads of per-thread equal-count ---
    int e = (u0 == thr) + (u1 == thr) + (u2 == thr) + (u3 == thr);
    int v = e;
#pragma unroll
    for (int d = 1; d < 32; d <<= 1) {
        int t = __shfl_up_sync(0xffffffffu, v, d);
        if (lane >= d) v += t;
    }
    if (lane == 31) s_scan[wid] = v;
    __syncthreads();
    if (wid == 0) {
        int w = s_scan[lane];
#pragma unroll
        for (int d = 1; d < 32; d <<= 1) {
            int t = __shfl_up_sync(0xffffffffu, w, d);
            if (lane >= d) w += t;
        }
        s_scan[lane] = w;
    }
    __syncthreads();
    int excl = v - e + (wid ? s_scan[wid - 1] : 0);

    // --- mask nibble for n = 4j..4j+3 ---
    unsigned nib = 0;
    int r = excl;
    unsigned uu[4] = {u0, u1, u2, u3};
#pragma unroll
    for (int i = 0; i < 4; ++i) {
        if (uu[i] > thr) {
            nib |= 1u << i;
        } else if (uu[i] == thr) {
            if (r < need) nib |= 1u << i;
            ++r;
        }
    }
    atomicOr(&s_mask[j >> 3], nib << ((j & 7) * 4));
    __syncthreads();
    if (j < NN / 32) g_maskbits[b * (NN / 32) + j] = s_mask[j];
}

// ---------------------------------------------------------------------------
// K1: per-chunk scoring (partials) + fused per-batch select in the LAST block
// of each batch (threadfence + atomic counter; counter self-resets for graph
// replay). Grid = 128 blocks x 1024 threads; blocks [0,64) = batch 2c,
// blocks [64,128) = batch 2c+1. Each thread: one (b,t,n) partial, 64 loads.
// ---------------------------------------------------------------------------
__global__ void __launch_bounds__(1024) k1_score_select(const float* __restrict__ x,
                                                        int chunk) {
    const int idx_local = blockIdx.x * 1024 + threadIdx.x;   // [0, 131072)
    const int n        = idx_local & (NN - 1);
    const int bt_local = idx_local >> 12;                    // 0..31
    const int b        = chunk * CHUNKB + (bt_local >> 4);
    const int bt       = chunk * (CHUNKB * TT) + bt_local;   // global b*TT + t

    const float* p = x + (size_t)bt * CC * NN + n;
    float acc = 0.0f;
#pragma unroll
    for (int c = 0; c < CC; ++c) {
        float v = p[(size_t)c * NN];
        acc += v * v;
    }
    g_partial[(size_t)bt * NN + n] = sqrtf(acc);

    // --- last-block-per-batch detection (canonical threadfence pattern) ---
    __shared__ int s_last;
    __syncthreads();
    if (threadIdx.x == 0) {
        __threadfence();
        int vv = atomicAdd(&g_cnt[b], 1);
        s_last = (vv == BLKS_PER_BATCH - 1);
        if (s_last) g_cnt[b] = 0;          // self-reset for next graph replay
    }
    __syncthreads();
    if (!s_last) return;

    __threadfence();                        // acquire: see all partial writes
    select_body(b);
}

// ---------------------------------------------------------------------------
// M: masked copy for one chunk. Reads should be L2 hits (x[chunk] streamed in
// by K1(chunk), window < L2 capacity). __ldcs/__stcs keep both streams
// evict-first so they don't pollute the next chunk's residency.
// ---------------------------------------------------------------------------
__global__ void __launch_bounds__(256) k_mask(const float4* __restrict__ x4,
                                              float4* __restrict__ o4,
                                              int chunk) {
    unsigned i = (unsigned)chunk * (CHUNKB * TT * CC * NN / 4)
               + blockIdx.x * 256 + threadIdx.x;
    int n4 = i & ((NN / 4) - 1);
    int b  = i >> 20;                        // 2^20 float4 per batch
    int n  = n4 << 2;
    unsigned mword = g_maskbits[(b << 7) + (n >> 5)];
    unsigned bits  = mword >> (n & 31);
    float4 v = __ldcs(&x4[(size_t)i]);
    v.x = (bits & 1u) ? v.x : 0.0f;
    v.y = (bits & 2u) ? v.y : 0.0f;
    v.z = (bits & 4u) ? v.z : 0.0f;
    v.w = (bits & 8u) ? v.w : 0.0f;
    __stcs(&o4[(size_t)i], v);
}

// ---------------------------------------------------------------------------
extern "C" void kernel_launch(void* const* d_in, const int* in_sizes, int n_in,
                              void* d_out, int out_size) {
    const float* x = (const float*)d_in[0];
    float* out = (float*)d_out;

    const int K1_GRID = CHUNKB * TT * NN / 1024;          // 128 blocks
    const int M_GRID  = CHUNKB * TT * CC * NN / 4 / 256;  // 8192 blocks

    // Software pipeline: M(c) runs one chunk behind K1, so x[c] is still
    // L2-resident when M(c) re-reads it.
    k1_score_select<<<K1_GRID, 1024>>>(x, 0);
    k1_score_select<<<K1_GRID, 1024>>>(x, 1);
    k_mask<<<M_GRID, 256>>>((const float4*)x, (float4*)out, 0);
    k1_score_select<<<K1_GRID, 1024>>>(x, 2);
    k_mask<<<M_GRID, 256>>>((const float4*)x, (float4*)out, 1);
    k1_score_select<<<K1_GRID, 1024>>>(x, 3);
    k_mask<<<M_GRID, 256>>>((const float4*)x, (float4*)out, 2);
    k_mask<<<M_GRID, 256>>>((const float4*)x, (float4*)out, 3);
}